// round 10
// baseline (speedup 1.0000x reference)
#include <cuda_runtime.h>
#include <cuda_bf16.h>
#include <cstdint>

// ===========================================================================
// BaoCypherNet on GB300 — tcgen05 bf16(hi/lo) gather-GEMM, persistent CTAs,
// double-buffered MMA pipeline, COALESCED gather via K-reorder + node-major
// activations. Inter-layer data = packed u32 {hi bf16 | lo bf16<<16}, layout
// [b][node][ch]; node 0 = normalized zero value, node n>=1 = conv position n-1.
// K order: k' = kr*CIN + ch  =>  a 64-chunk of k' is 64 consecutive channels
// at a single node per row => gather is contiguous 256B per row.
// Layer-3 epilogue fuses maxpool + 64->32->1 MLP (scale>0 => max commutes).
// ===========================================================================

#if defined(__CUDA_ARCH__) && (defined(__CUDA_ARCH_FEAT_SM103_ALL) || defined(__CUDA_ARCH_FEAT_SM100_ALL))
#define HAS_TCGEN05 1
#else
#define HAS_TCGEN05 0
#endif

#define B_TREES 2048
#define GRID_P  148

// ----------------------------- scratch -------------------------------------
__device__ uint32_t g_X0[(size_t)2048 * 128 * 128];   // packed trees [b][node][ch]
__device__ uint32_t g_X1[(size_t)2048 * 128 * 256];   // packed L1 out [b][node][256]
__device__ uint32_t g_X2[(size_t)2048 * 128 * 128];   // packed L2 out [b][node][128]
__device__ float    g_raw[(size_t)2048 * 256 * 128];  // fallback-only scratch
// pre-split, pre-SW128-swizzled weight images (k' = kr*CIN+ch order);
// per (chunk, half128) 16KB block.
__device__ __nv_bfloat16 g_W1h[6 * 2 * 128 * 64], g_W1l[6 * 2 * 128 * 64];
__device__ __nv_bfloat16 g_W2h[12 * 128 * 64],    g_W2l[12 * 128 * 64];
__device__ __nv_bfloat16 g_W3h[6 * 128 * 64],     g_W3l[6 * 128 * 64];

__device__ __forceinline__ uint32_t swz(uint32_t byte_off) {
    return byte_off ^ ((byte_off >> 3) & 0x70);
}
__device__ __forceinline__ uint32_t pack_hl(float x) {
    __nv_bfloat16 h = __float2bfloat16(x);
    __nv_bfloat16 l = __float2bfloat16(x - __bfloat162float(h));
    return (uint32_t)__bfloat16_as_ushort(h) | ((uint32_t)__bfloat16_as_ushort(l) << 16);
}
__device__ __forceinline__ float unpack_hl(uint32_t p) {
    __nv_bfloat16 h = __ushort_as_bfloat16((unsigned short)(p & 0xFFFF));
    __nv_bfloat16 l = __ushort_as_bfloat16((unsigned short)(p >> 16));
    return __bfloat162float(h) + __bfloat162float(l);
}
__device__ __forceinline__ float leaky(float a) { return a > 0.f ? a : 0.01f * a; }

#if HAS_TCGEN05
// ----------------------------- PTX helpers (sm_103a only) -------------------
__device__ __forceinline__ uint32_t smem_u32(const void* p) {
    uint32_t a;
    asm("{ .reg .u64 t; cvta.to.shared.u64 t, %1; cvt.u32.u64 %0, t; }"
        : "=r"(a) : "l"(p));
    return a;
}
__device__ __forceinline__ uint32_t elect_one() {
    uint32_t p;
    asm volatile("{ .reg .pred p; elect.sync _|p, 0xFFFFFFFF; selp.b32 %0,1,0,p; }"
                 : "=r"(p));
    return p;
}

#define TCGEN05_ALLOC(sm_addr, n) \
    asm volatile("tcgen05.alloc.cta_group::1.sync.aligned.shared::cta.b32 [%0], %1;" \
                 :: "r"((uint32_t)(sm_addr)), "r"((uint32_t)(n)) : "memory")
#define TCGEN05_DEALLOC(tm, n) \
    asm volatile("tcgen05.dealloc.cta_group::1.sync.aligned.b32 %0, %1;" :: "r"(tm), "r"((uint32_t)(n)))
#define TCGEN05_RELINQ() \
    asm volatile("tcgen05.relinquish_alloc_permit.cta_group::1.sync.aligned;")
#define TCGEN05_COMMIT(mbar) \
    asm volatile("tcgen05.commit.cta_group::1.mbarrier::arrive::one.shared::cluster.b64 [%0];" \
                 :: "r"((uint32_t)(mbar)) : "memory")
#define TCGEN05_WAIT_LD()  asm volatile("tcgen05.wait::ld.sync.aligned;" ::: "memory")
#define TCGEN05_FENCE_AFTER()  asm volatile("tcgen05.fence::after_thread_sync;" ::: "memory")
#define TCGEN05_FENCE_BEFORE() asm volatile("tcgen05.fence::before_thread_sync;" ::: "memory")
#define FENCE_ASYNC_SHARED() asm volatile("fence.proxy.async.shared::cta;" ::: "memory")
#define MBARRIER_INIT(mbar, cnt) \
    asm volatile("mbarrier.init.shared.b64 [%0], %1;" :: "r"((uint32_t)(mbar)), "r"((uint32_t)(cnt)) : "memory")
#define MBARRIER_INVAL(mbar) \
    asm volatile("mbarrier.inval.shared.b64 [%0];" :: "r"((uint32_t)(mbar)) : "memory")

#define MBARRIER_WAIT_PARITY(mbar_addr, parity) do {                               \
    uint32_t _m = (uint32_t)(mbar_addr);                                           \
    uint32_t _p = (uint32_t)(parity);                                              \
    uint32_t _done;                                                                \
    asm volatile("{\n\t.reg .pred p;\n\t"                                          \
        "mbarrier.try_wait.parity.acquire.cta.shared::cta.b64 p, [%1], %2;\n\t"    \
        "selp.b32 %0, 1, 0, p;\n\t}"                                               \
        : "=r"(_done) : "r"(_m), "r"(_p) : "memory");                              \
    if (!_done) {                                                                  \
        asm volatile("{\n\t.reg .pred P1;\n\t"                                     \
            "WL_%=:\n\t"                                                           \
            "mbarrier.try_wait.parity.acquire.cta.shared::cta.b64 P1, [%0], %1, 0x989680;\n\t" \
            "@P1 bra.uni WD_%=;\n\t"                                               \
            "bra.uni WL_%=;\n\t"                                                   \
            "WD_%=:\n\t}" :: "r"(_m), "r"(_p) : "memory");                         \
    }                                                                              \
} while (0)

#define TCGEN05_LD_X32(r, addr) \
    asm volatile("tcgen05.ld.sync.aligned.32x32b.x32.b32 " \
        "{%0, %1, %2, %3, %4, %5, %6, %7, %8, %9, %10, %11, %12, %13, %14, %15, " \
        " %16, %17, %18, %19, %20, %21, %22, %23, %24, %25, %26, %27, %28, %29, %30, %31}, [%32];" \
        : "=r"((r)[0]),  "=r"((r)[1]),  "=r"((r)[2]),  "=r"((r)[3]),  \
          "=r"((r)[4]),  "=r"((r)[5]),  "=r"((r)[6]),  "=r"((r)[7]),  \
          "=r"((r)[8]),  "=r"((r)[9]),  "=r"((r)[10]), "=r"((r)[11]), \
          "=r"((r)[12]), "=r"((r)[13]), "=r"((r)[14]), "=r"((r)[15]), \
          "=r"((r)[16]), "=r"((r)[17]), "=r"((r)[18]), "=r"((r)[19]), \
          "=r"((r)[20]), "=r"((r)[21]), "=r"((r)[22]), "=r"((r)[23]), \
          "=r"((r)[24]), "=r"((r)[25]), "=r"((r)[26]), "=r"((r)[27]), \
          "=r"((r)[28]), "=r"((r)[29]), "=r"((r)[30]), "=r"((r)[31]) \
        : "r"(addr))

#define STS64(addr, a0, a1) \
    asm volatile("st.shared.v2.b32 [%0], {%1, %2};" \
                 :: "r"(addr), "r"(a0), "r"(a1) : "memory")

// SW128 descriptor (LBO=1, SBO=64, version=1): rows of 128B, K-major.
__device__ __forceinline__ uint64_t mk_desc(uint32_t addr) {
    constexpr uint64_t BASE = (2ull << 61) | (1ull << 46) | (64ull << 32) | (1ull << 16);
    return BASE | ((uint64_t)(addr >> 4) & 0x3FFF);
}

// cg1 kind::f16 SS MMA (bf16 in, fp32 acc)
__device__ __forceinline__ void mma_f16_ss(uint32_t d, uint64_t a, uint64_t b,
                                           uint32_t idesc, bool acc) {
    uint32_t en = acc ? 1u : 0u;
    asm volatile("{\n\t.reg .pred p;\n\tsetp.ne.u32 p, %5, 0;\n\t"
        "tcgen05.mma.cta_group::1.kind::f16 [%0], %1, %2, %3, {%4, %4, %4, %4}, p;\n\t}"
        :: "r"(d), "l"(a), "l"(b), "r"(idesc), "r"(0u), "r"(en) : "memory");
}
#endif // HAS_TCGEN05

// --------------------------- prep kernels -----------------------------------
// Weight images in k' = kr*CIN + ch order (matches node-major gather).
__global__ void prep_w_kernel(const float* __restrict__ W1,
                              const float* __restrict__ W2,
                              const float* __restrict__ W3) {
    int bid = blockIdx.x;
    const float* W; __nv_bfloat16 *gh, *gl; int COUT, CIN, chunk, HALVES;
    if (bid < 6)       { W = W1; gh = g_W1h; gl = g_W1l; COUT = 256; CIN = 128; chunk = bid;      HALVES = 2; }
    else if (bid < 18) { W = W2; gh = g_W2h; gl = g_W2l; COUT = 128; CIN = 256; chunk = bid - 6;  HALVES = 1; }
    else               { W = W3; gh = g_W3h; gl = g_W3l; COUT = 64;  CIN = 128; chunk = bid - 18; HALVES = 1; }
    const int ROWS = HALVES * 128;
    const int K = 3 * CIN;
    const int kr  = (chunk * 64) / CIN;
    const int ch0 = chunk * 64 - kr * CIN;
    char* bh = (char*)gh + (size_t)chunk * HALVES * 16384;
    char* bl = (char*)gl + (size_t)chunk * HALVES * 16384;
    for (int i = threadIdx.x; i < ROWS * 64; i += blockDim.x) {
        int o = i >> 6, k = i & 63;
        float w = (o < COUT) ? W[(size_t)o * K + (ch0 + k) * 3 + kr] : 0.f;
        __nv_bfloat16 h = __float2bfloat16(w);
        __nv_bfloat16 l = __float2bfloat16(w - __bfloat162float(h));
        uint32_t off = (uint32_t)(o >> 7) * 16384u + swz((uint32_t)((o & 127) * 128 + k * 2));
        *(__nv_bfloat16*)(bh + off) = h;
        *(__nv_bfloat16*)(bl + off) = l;
    }
}

// Transpose + pack trees: [b][c][n] -> g_X0 [b][n][c], via 32x33 smem tiles.
__global__ void prep_x_kernel(const float* __restrict__ trees) {
    __shared__ float tile[32][33];
    const int b = blockIdx.x;
    const int w = threadIdx.x >> 5, l = threadIdx.x & 31;
    const float* Tb = trees + (size_t)b * 16384;
    uint32_t* Xb = g_X0 + (size_t)b * 16384;
    for (int tc = 0; tc < 4; tc++)
        for (int tn = 0; tn < 4; tn++) {
            __syncthreads();
            #pragma unroll
            for (int rr = 0; rr < 4; rr++) {
                int r = w + rr * 8;
                tile[r][l] = Tb[(tc * 32 + r) * 128 + tn * 32 + l];
            }
            __syncthreads();
            #pragma unroll
            for (int rr = 0; rr < 4; rr++) {
                int r = w + rr * 8;
                Xb[(tn * 32 + r) * 128 + tc * 32 + l] = pack_hl(tile[l][r]);
            }
        }
}

// ------------------------------ conv layer (persistent) ---------------------
template <int CIN, int COUT, int LAYER>
__global__ __launch_bounds__(256, 1) void conv_tc(
    const int*   __restrict__ indexes,
    const float* __restrict__ Wraw,          // fallback only
    const float* __restrict__ bias,
    const float* __restrict__ W4, const float* __restrict__ b4,
    const float* __restrict__ W5, const float* __restrict__ b5,
    float* __restrict__ out)
{
    constexpr int K = 3 * CIN;
    constexpr int NCHUNK = K / 64;
    constexpr int HALVES = (COUT + 127) / 128;
    constexpr int A_BYTES = HALVES * 16384;           // one precision
    constexpr int AB_STAGE = 2 * A_BYTES + 32768;     // Ah+Al+Bh+Bl per stage
    constexpr int TBYTES = COUT * 129 * 4;
    constexpr int REGION = (2 * AB_STAGE > TBYTES) ? 2 * AB_STAGE : TBYTES;
    constexpr int OFF_IDX = REGION;
    constexpr int OFF_MBAR = OFF_IDX + 1536;
    constexpr int OFF_RED = OFF_MBAR + 48;

    extern __shared__ __align__(1024) char smem[];
    int*   sidx  = (int*)(smem + OFF_IDX);
    float* snorm = (float*)(smem + OFF_MBAR + 16);
    float* sred  = (float*)(smem + OFF_RED);

    const int tid = threadIdx.x, wid = tid >> 5, lid = tid & 31;

    const uint32_t* __restrict__ Xin =
        (LAYER == 1) ? g_X0 : (LAYER == 2) ? g_X1 : g_X2;
    uint32_t* __restrict__ Xout = (LAYER == 1) ? g_X1 : g_X2;

#if HAS_TCGEN05
    // ===================== tcgen05 tensor-core path =========================
    constexpr uint32_t IDESC = (1u << 4) | (1u << 7) | (1u << 10)
                             | (8u << 17) | (8u << 24);   // f32acc bf16 N=64 M=128
    constexpr int NCOLS = HALVES * 128;

    const uint32_t sb = smem_u32(smem);

    if (wid == 0) { TCGEN05_ALLOC(sb + OFF_MBAR + 32, NCOLS); }
    if (tid == 0) { MBARRIER_INIT(sb + OFF_MBAR, 1); MBARRIER_INIT(sb + OFF_MBAR + 8, 1); }
    __syncthreads();
    const uint32_t tmem = *(volatile uint32_t*)(smem + OFF_MBAR + 32);

    const char* gWh = (LAYER == 1) ? (const char*)g_W1h :
                      (LAYER == 2) ? (const char*)g_W2h : (const char*)g_W3h;
    const char* gWl = (LAYER == 1) ? (const char*)g_W1l :
                      (LAYER == 2) ? (const char*)g_W2l : (const char*)g_W3l;

    int use[2] = {0, 0};

    for (int b = blockIdx.x; b < B_TREES; b += GRID_P) {
        const uint32_t* __restrict__ Xb = Xin + (size_t)b * 128 * CIN;

        for (int i = tid; i < 384; i += 256)
            sidx[i] = (i < 381) ? indexes[b * 381 + i] : 0;
        __syncthreads();

        for (int c0 = 0; c0 < NCHUNK; c0++) {
            const int s = c0 & 1;
            const int SA = s * AB_STAGE;
            const int OFF_AH = SA, OFF_AL = SA + A_BYTES;
            const int OFF_BH = SA + 2 * A_BYTES, OFF_BL = SA + 2 * A_BYTES + 16384;
            const int kr  = (c0 * 64) / CIN;
            const int ch0 = c0 * 64 - kr * CIN;

            if (use[s] > 0)
                MBARRIER_WAIT_PARITY(sb + OFF_MBAR + s * 8, (use[s] - 1) & 1);

            // ---- A: straight copy of pre-swizzled W chunk (hi + lo) ----
            {
                const uint4* sh = (const uint4*)(gWh + (size_t)c0 * A_BYTES);
                const uint4* sl = (const uint4*)(gWl + (size_t)c0 * A_BYTES);
                uint4* dh = (uint4*)(smem + OFF_AH);
                uint4* dl = (uint4*)(smem + OFF_AL);
                for (int i = tid; i < A_BYTES / 16; i += 256) { dh[i] = sh[i]; dl[i] = sl[i]; }
            }
            // ---- B: coalesced gather. Row n = 64 consecutive channels at one
            //      node. Lanes: 16 lanes x uint4 cover one row's 256B; 2 rows
            //      per warp-LDG -> 4 cache lines per instruction. ----
            {
                const int nl = lid >> 4;           // 0/1: which row in the pair
                const int q  = lid & 15;           // uint4 index within row
                #pragma unroll
                for (int it = 0; it < 8; it++) {
                    int n = it * 16 + wid * 2 + nl;
                    int node = sidx[n * 3 + kr];
                    uint4 v = *(const uint4*)(Xb + (size_t)node * CIN + ch0 + q * 4);
                    uint32_t h0 = __byte_perm(v.x, v.y, 0x5410);
                    uint32_t h1 = __byte_perm(v.z, v.w, 0x5410);
                    uint32_t l0 = __byte_perm(v.x, v.y, 0x7632);
                    uint32_t l1 = __byte_perm(v.z, v.w, 0x7632);
                    uint32_t off = swz((uint32_t)(n * 128 + q * 8));
                    STS64(sb + OFF_BH + off, h0, h1);
                    STS64(sb + OFF_BL + off, l0, l1);
                }
            }
            FENCE_ASYNC_SHARED();
            __syncthreads();

            // ---- issue MMAs for this chunk (M=128, N=64 each) ----
            if (wid == 0 && elect_one()) {
                TCGEN05_FENCE_AFTER();
                #pragma unroll
                for (int h = 0; h < HALVES; h++) {
                    uint64_t adh = mk_desc(sb + OFF_AH + h * 16384);
                    uint64_t adl = mk_desc(sb + OFF_AL + h * 16384);
                    #pragma unroll
                    for (int nh = 0; nh < 2; nh++) {
                        uint32_t d = tmem + h * 128 + nh * 64;
                        uint64_t bdh = mk_desc(sb + OFF_BH + nh * 8192);
                        uint64_t bdl = mk_desc(sb + OFF_BL + nh * 8192);
                        #pragma unroll
                        for (int q = 0; q < 3; q++) {        // hh, lh, hl
                            uint64_t ad = (q == 1) ? adl : adh;
                            uint64_t bd = (q == 2) ? bdl : bdh;
                            #pragma unroll
                            for (int km = 0; km < 4; km++) {
                                bool acc = !(c0 == 0 && q == 0 && km == 0);
                                mma_f16_ss(d, ad + km * 2, bd + km * 2, IDESC, acc);
                            }
                        }
                    }
                }
                TCGEN05_COMMIT(sb + OFF_MBAR + s * 8);
            }
            use[s]++;
        }

        // ---- drain both buffers, then epilogue ----
        #pragma unroll
        for (int s = 0; s < 2; s++)
            if (use[s] > 0)
                MBARRIER_WAIT_PARITY(sb + OFF_MBAR + s * 8, (use[s] - 1) & 1);
        TCGEN05_FENCE_AFTER();

        // pass 1: LDTM once, stash raw+bias into T (col0 = 0), stats
        float* T = (float*)smem;
        float s1 = 0.f, s2 = 0.f;
        constexpr int NWARP = (LAYER == 3) ? 2 : 4;
        if (wid < NWARP) {
            #pragma unroll
            for (int h = 0; h < HALVES; h++) {
                int row = wid * 32 + lid;
                int o = h * 128 + row;
                if (o < COUT) {
                    float bv = bias[o];
                    float* Tr = T + o * 129;
                    Tr[0] = 0.f;
                    #pragma unroll
                    for (int nb = 0; nb < 4; nb++) {
                        uint32_t r[32];
                        TCGEN05_LD_X32(r, tmem + h * 128 + nb * 32);
                        TCGEN05_WAIT_LD();
                        #pragma unroll
                        for (int q = 0; q < 32; q++) {
                            int n = nb * 32 + q;
                            if (n < 127) {
                                float val = __uint_as_float(r[q]) + bv;
                                Tr[n + 1] = val;
                                s1 += val; s2 += val * val;
                            }
                        }
                    }
                }
            }
            TCGEN05_FENCE_BEFORE();
        }
        sred[tid] = s1; sred[256 + tid] = s2;
        __syncthreads();
        #pragma unroll
        for (int st = 128; st > 0; st >>= 1) {
            if (tid < st) { sred[tid] += sred[tid + st]; sred[256 + tid] += sred[256 + tid + st]; }
            __syncthreads();
        }
        if (tid == 0) {
            constexpr float np = (float)(COUT * 128);
            float t1 = sred[0], t2 = sred[256];
            float mmu = t1 / np;
            float var = fmaxf((t2 - t1 * mmu) / (np - 1.f), 0.f);
            snorm[0] = mmu;
            snorm[1] = 1.f / (sqrtf(var) + 1e-5f);
        }
        __syncthreads();
        const float mu = snorm[0], scale = snorm[1];

        if (LAYER < 3) {
            // pass 2: normalize + leaky + pack, store NODE-MAJOR (coalesced in o)
            for (int i = tid; i < 128 * COUT; i += 256) {
                int node = i / COUT, o = i - node * COUT;
                float v = (T + o * 129)[node];     // stride 129: conflict-free
                Xout[((size_t)b * 128 + node) * COUT + o] =
                    pack_hl(leaky((v - mu) * scale));
            }
        } else {
            // fused maxpool + MLP  (LN3 has no leaky; scale>0 => max commutes)
            float* pooled = sred;
            float* hbuf = sred + 96;
            if (tid < 64) {
                const float* Tr = T + tid * 129;
                float mx = Tr[0];
                #pragma unroll
                for (int c = 1; c < 128; c++) mx = fmaxf(mx, Tr[c]);
                pooled[tid] = (mx - mu) * scale;
            }
            __syncthreads();
            if (tid < 32) {
                float acc = b4[tid];
                #pragma unroll
                for (int c = 0; c < 64; c++) acc += pooled[c] * W4[tid * 64 + c];
                hbuf[tid] = leaky(acc);
            }
            __syncthreads();
            if (tid < 32) {
                float p = hbuf[tid] * W5[tid];
                #pragma unroll
                for (int off = 16; off; off >>= 1) p += __shfl_down_sync(0xffffffffu, p, off);
                if (tid == 0) out[b] = p + b5[0];
            }
        }
        __syncthreads();
    }

    // ---- one-time teardown ----
    if (tid == 0) { MBARRIER_INVAL(sb + OFF_MBAR); MBARRIER_INVAL(sb + OFF_MBAR + 8); }
    __syncthreads();
    if (wid == 0) { TCGEN05_RELINQ(); TCGEN05_DEALLOC(tmem, NCOLS); }

#else
    // ===================== SIMT fp32 fallback (generic target) ==============
    float* Ws  = (float*)smem;                  // 64 x 32
    float* Bsf = (float*)(smem + 8192);         // 32 x 68 (padded)
    const int tx = tid & 15, ty = tid >> 4;

    for (int b = blockIdx.x; b < B_TREES; b += GRID_P) {
        const uint32_t* __restrict__ Xb = Xin + (size_t)b * 128 * CIN;
        __syncthreads();
        for (int i = tid; i < 384; i += 256)
            sidx[i] = (i < 381) ? indexes[b * 381 + i] : 0;
        __syncthreads();
        float s1 = 0.f, s2 = 0.f;

        for (int ot = 0; ot < COUT / 64; ot++) {
            for (int mt = 0; mt < 2; mt++) {
                float acc[4][4];
                #pragma unroll
                for (int i = 0; i < 4; i++)
                    #pragma unroll
                    for (int j = 0; j < 4; j++) acc[i][j] = 0.f;
                int o0 = ot * 64, m0 = mt * 64;
                for (int k0 = 0; k0 < K; k0 += 32) {
                    __syncthreads();
                    for (int i = tid; i < 2048; i += 256) {
                        int r = i >> 5, kk = i & 31;
                        Ws[r * 32 + kk] = Wraw[(size_t)(o0 + r) * K + k0 + kk];
                    }
                    for (int i = tid; i < 2048; i += 256) {
                        int kk = i >> 6, n = i & 63;
                        int j = k0 + kk;
                        int ch = j / 3, kr = j - 3 * ch;
                        int node = sidx[(m0 + n) * 3 + kr];
                        Bsf[kk * 68 + n] = unpack_hl(Xb[(size_t)node * CIN + ch]);
                    }
                    __syncthreads();
                    #pragma unroll
                    for (int kk = 0; kk < 32; kk++) {
                        float bvv[4];
                        #pragma unroll
                        for (int j = 0; j < 4; j++) bvv[j] = Bsf[kk * 68 + tx * 4 + j];
                        #pragma unroll
                        for (int i = 0; i < 4; i++) {
                            float av = Ws[(ty * 4 + i) * 32 + kk];
                            #pragma unroll
                            for (int j = 0; j < 4; j++) acc[i][j] += av * bvv[j];
                        }
                    }
                }
                __syncthreads();
                #pragma unroll
                for (int i = 0; i < 4; i++) {
                    int o = o0 + ty * 4 + i;
                    float bv = bias[o];
                    #pragma unroll
                    for (int j = 0; j < 4; j++) {
                        int m = m0 + tx * 4 + j;
                        if (m < 127) {
                            float val = acc[i][j] + bv;
                            g_raw[((size_t)b * COUT + o) * 128 + m] = val;
                            s1 += val; s2 += val * val;
                        }
                    }
                }
            }
        }
        sred[tid] = s1; sred[256 + tid] = s2;
        __syncthreads();
        #pragma unroll
        for (int st = 128; st > 0; st >>= 1) {
            if (tid < st) { sred[tid] += sred[tid + st]; sred[256 + tid] += sred[256 + tid + st]; }
            __syncthreads();
        }
        if (tid == 0) {
            float np = (float)(COUT * 128);
            float t1 = sred[0], t2 = sred[256];
            float mmu = t1 / np;
            float var = fmaxf((t2 - t1 * mmu) / (np - 1.f), 0.f);
            snorm[0] = mmu;
            snorm[1] = 1.f / (sqrtf(var) + 1e-5f);
        }
        __syncthreads();
        float mu = snorm[0], scale = snorm[1];

        if (LAYER < 3) {
            for (int i = tid; i < 128 * COUT; i += 256) {
                int node = i / COUT, o = i - node * COUT;
                float v = (node == 0) ? 0.f : g_raw[((size_t)b * COUT + o) * 128 + node - 1];
                Xout[((size_t)b * 128 + node) * COUT + o] = pack_hl(leaky((v - mu) * scale));
            }
        } else {
            float* pooled = sred;
            float* hbuf = sred + 96;
            if (tid < 64) {
                float mx = 0.f;
                for (int m = 0; m < 127; m++)
                    mx = fmaxf(mx, g_raw[((size_t)b * 64 + tid) * 128 + m]);
                pooled[tid] = (mx - mu) * scale;
            }
            __syncthreads();
            if (tid < 32) {
                float acc = b4[tid];
                #pragma unroll
                for (int c = 0; c < 64; c++) acc += pooled[c] * W4[tid * 64 + c];
                hbuf[tid] = leaky(acc);
            }
            __syncthreads();
            if (tid < 32) {
                float p = hbuf[tid] * W5[tid];
                #pragma unroll
                for (int off = 16; off; off >>= 1) p += __shfl_down_sync(0xffffffffu, p, off);
                if (tid == 0) out[b] = p + b5[0];
            }
        }
        __syncthreads();
    }
#endif
}

// ---------------------------------------------------------------------------
extern "C" void kernel_launch(void* const* d_in, const int* in_sizes, int n_in,
                              void* d_out, int out_size)
{
    const float *trees, *W1, *b1, *W2, *b2, *W3, *b3, *W4, *b4, *W5, *b5;
    const int* indexes;

    if (in_sizes[1] == 3 * 127 * B_TREES) {
        trees   = (const float*)d_in[0];
        indexes = (const int*)  d_in[1];
        W1 = (const float*)d_in[2];  b1 = (const float*)d_in[3];
        W2 = (const float*)d_in[4];  b2 = (const float*)d_in[5];
        W3 = (const float*)d_in[6];  b3 = (const float*)d_in[7];
        W4 = (const float*)d_in[8];  b4 = (const float*)d_in[9];
        W5 = (const float*)d_in[10]; b5 = (const float*)d_in[11];
    } else {
        trees = (const float*)d_in[0];
        W1 = (const float*)d_in[1];  b1 = (const float*)d_in[2];
        W2 = (const float*)d_in[3];  b2 = (const float*)d_in[4];
        W3 = (const float*)d_in[5];  b3 = (const float*)d_in[6];
        W4 = (const float*)d_in[7];  b4 = (const float*)d_in[8];
        W5 = (const float*)d_in[9];  b5 = (const float*)d_in[10];
        indexes = (const int*)d_in[11];
    }
    float* out = (float*)d_out;

    const int SMEM1 = 196608 + 1536 + 48 + 2048;   // 200240
    const int SMEM2 = 131072 + 1536 + 48 + 2048;   // 134704
    cudaFuncSetAttribute(conv_tc<128, 256, 1>, cudaFuncAttributeMaxDynamicSharedMemorySize, SMEM1);
    cudaFuncSetAttribute(conv_tc<256, 128, 2>, cudaFuncAttributeMaxDynamicSharedMemorySize, SMEM2);
    cudaFuncSetAttribute(conv_tc<128, 64, 3>,  cudaFuncAttributeMaxDynamicSharedMemorySize, SMEM2);

    prep_w_kernel<<<24, 256>>>(W1, W2, W3);
    prep_x_kernel<<<B_TREES, 256>>>(trees);
    conv_tc<128, 256, 1><<<GRID_P, 256, SMEM1>>>(indexes, W1, b1, nullptr, nullptr, nullptr, nullptr, nullptr);
    conv_tc<256, 128, 2><<<GRID_P, 256, SMEM2>>>(indexes, W2, b2, nullptr, nullptr, nullptr, nullptr, nullptr);
    conv_tc<128, 64, 3><<<GRID_P, 256, SMEM2>>>(indexes, W3, b3, W4, b4, W5, b5, out);
}

// round 11
// speedup vs baseline: 2.3957x; 2.3957x over previous
#include <cuda_runtime.h>
#include <cuda_bf16.h>
#include <cstdint>

// ===========================================================================
// BaoCypherNet on GB300 — tcgen05 bf16(hi/lo) gather-GEMM, persistent CTAs,
// double-buffered MMA pipeline, coalesced gather (K-reorder + node-major X),
// register node-table + one-chunk-ahead register prefetch of B, cp.async A.
// Inter-layer data = packed u32 {hi bf16 | lo bf16<<16}, layout [b][node][ch];
// node 0 = normalized zero value, node n>=1 = conv position n-1.
// K order: k' = kr*CIN + ch. Layer-3 epilogue fuses maxpool + 64->32->1 MLP.
// ===========================================================================

#if defined(__CUDA_ARCH__) && (defined(__CUDA_ARCH_FEAT_SM103_ALL) || defined(__CUDA_ARCH_FEAT_SM100_ALL))
#define HAS_TCGEN05 1
#else
#define HAS_TCGEN05 0
#endif

#define B_TREES 2048
#define GRID_P  148

// ----------------------------- scratch -------------------------------------
__device__ uint32_t g_X0[(size_t)2048 * 128 * 128];   // packed trees [b][node][ch]
__device__ uint32_t g_X1[(size_t)2048 * 128 * 256];   // packed L1 out [b][node][256]
__device__ uint32_t g_X2[(size_t)2048 * 128 * 128];   // packed L2 out [b][node][128]
__device__ float    g_raw[(size_t)2048 * 256 * 128];  // fallback-only scratch
// pre-split, pre-SW128-swizzled weight images (k' = kr*CIN+ch order);
// per (chunk, half128) 16KB block.
__device__ __nv_bfloat16 g_W1h[6 * 2 * 128 * 64], g_W1l[6 * 2 * 128 * 64];
__device__ __nv_bfloat16 g_W2h[12 * 128 * 64],    g_W2l[12 * 128 * 64];
__device__ __nv_bfloat16 g_W3h[6 * 128 * 64],     g_W3l[6 * 128 * 64];

__device__ __forceinline__ uint32_t swz(uint32_t byte_off) {
    return byte_off ^ ((byte_off >> 3) & 0x70);
}
__device__ __forceinline__ uint32_t pack_hl(float x) {
    __nv_bfloat16 h = __float2bfloat16(x);
    __nv_bfloat16 l = __float2bfloat16(x - __bfloat162float(h));
    return (uint32_t)__bfloat16_as_ushort(h) | ((uint32_t)__bfloat16_as_ushort(l) << 16);
}
__device__ __forceinline__ float unpack_hl(uint32_t p) {
    __nv_bfloat16 h = __ushort_as_bfloat16((unsigned short)(p & 0xFFFF));
    __nv_bfloat16 l = __ushort_as_bfloat16((unsigned short)(p >> 16));
    return __bfloat162float(h) + __bfloat162float(l);
}
__device__ __forceinline__ float leaky(float a) { return a > 0.f ? a : 0.01f * a; }

#if HAS_TCGEN05
// ----------------------------- PTX helpers (sm_103a only) -------------------
__device__ __forceinline__ uint32_t smem_u32(const void* p) {
    uint32_t a;
    asm("{ .reg .u64 t; cvta.to.shared.u64 t, %1; cvt.u32.u64 %0, t; }"
        : "=r"(a) : "l"(p));
    return a;
}
__device__ __forceinline__ uint32_t elect_one() {
    uint32_t p;
    asm volatile("{ .reg .pred p; elect.sync _|p, 0xFFFFFFFF; selp.b32 %0,1,0,p; }"
                 : "=r"(p));
    return p;
}
__device__ __forceinline__ void cp_async16(uint32_t dst, const void* src) {
    asm volatile("cp.async.cg.shared.global [%0], [%1], 16;"
                 :: "r"(dst), "l"(src) : "memory");
}
#define CP_ASYNC_COMMIT() asm volatile("cp.async.commit_group;" ::: "memory")
#define CP_ASYNC_WAIT0()  asm volatile("cp.async.wait_group 0;" ::: "memory")

#define TCGEN05_ALLOC(sm_addr, n) \
    asm volatile("tcgen05.alloc.cta_group::1.sync.aligned.shared::cta.b32 [%0], %1;" \
                 :: "r"((uint32_t)(sm_addr)), "r"((uint32_t)(n)) : "memory")
#define TCGEN05_DEALLOC(tm, n) \
    asm volatile("tcgen05.dealloc.cta_group::1.sync.aligned.b32 %0, %1;" :: "r"(tm), "r"((uint32_t)(n)))
#define TCGEN05_RELINQ() \
    asm volatile("tcgen05.relinquish_alloc_permit.cta_group::1.sync.aligned;")
#define TCGEN05_COMMIT(mbar) \
    asm volatile("tcgen05.commit.cta_group::1.mbarrier::arrive::one.shared::cluster.b64 [%0];" \
                 :: "r"((uint32_t)(mbar)) : "memory")
#define TCGEN05_WAIT_LD()  asm volatile("tcgen05.wait::ld.sync.aligned;" ::: "memory")
#define TCGEN05_FENCE_AFTER()  asm volatile("tcgen05.fence::after_thread_sync;" ::: "memory")
#define TCGEN05_FENCE_BEFORE() asm volatile("tcgen05.fence::before_thread_sync;" ::: "memory")
#define FENCE_ASYNC_SHARED() asm volatile("fence.proxy.async.shared::cta;" ::: "memory")
#define MBARRIER_INIT(mbar, cnt) \
    asm volatile("mbarrier.init.shared.b64 [%0], %1;" :: "r"((uint32_t)(mbar)), "r"((uint32_t)(cnt)) : "memory")
#define MBARRIER_INVAL(mbar) \
    asm volatile("mbarrier.inval.shared.b64 [%0];" :: "r"((uint32_t)(mbar)) : "memory")

#define MBARRIER_WAIT_PARITY(mbar_addr, parity) do {                               \
    uint32_t _m = (uint32_t)(mbar_addr);                                           \
    uint32_t _p = (uint32_t)(parity);                                              \
    uint32_t _done;                                                                \
    asm volatile("{\n\t.reg .pred p;\n\t"                                          \
        "mbarrier.try_wait.parity.acquire.cta.shared::cta.b64 p, [%1], %2;\n\t"    \
        "selp.b32 %0, 1, 0, p;\n\t}"                                               \
        : "=r"(_done) : "r"(_m), "r"(_p) : "memory");                              \
    if (!_done) {                                                                  \
        asm volatile("{\n\t.reg .pred P1;\n\t"                                     \
            "WL_%=:\n\t"                                                           \
            "mbarrier.try_wait.parity.acquire.cta.shared::cta.b64 P1, [%0], %1, 0x989680;\n\t" \
            "@P1 bra.uni WD_%=;\n\t"                                               \
            "bra.uni WL_%=;\n\t"                                                   \
            "WD_%=:\n\t}" :: "r"(_m), "r"(_p) : "memory");                         \
    }                                                                              \
} while (0)

#define TCGEN05_LD_X32(r, addr) \
    asm volatile("tcgen05.ld.sync.aligned.32x32b.x32.b32 " \
        "{%0, %1, %2, %3, %4, %5, %6, %7, %8, %9, %10, %11, %12, %13, %14, %15, " \
        " %16, %17, %18, %19, %20, %21, %22, %23, %24, %25, %26, %27, %28, %29, %30, %31}, [%32];" \
        : "=r"((r)[0]),  "=r"((r)[1]),  "=r"((r)[2]),  "=r"((r)[3]),  \
          "=r"((r)[4]),  "=r"((r)[5]),  "=r"((r)[6]),  "=r"((r)[7]),  \
          "=r"((r)[8]),  "=r"((r)[9]),  "=r"((r)[10]), "=r"((r)[11]), \
          "=r"((r)[12]), "=r"((r)[13]), "=r"((r)[14]), "=r"((r)[15]), \
          "=r"((r)[16]), "=r"((r)[17]), "=r"((r)[18]), "=r"((r)[19]), \
          "=r"((r)[20]), "=r"((r)[21]), "=r"((r)[22]), "=r"((r)[23]), \
          "=r"((r)[24]), "=r"((r)[25]), "=r"((r)[26]), "=r"((r)[27]), \
          "=r"((r)[28]), "=r"((r)[29]), "=r"((r)[30]), "=r"((r)[31]) \
        : "r"(addr))

#define STS64(addr, a0, a1) \
    asm volatile("st.shared.v2.b32 [%0], {%1, %2};" \
                 :: "r"(addr), "r"(a0), "r"(a1) : "memory")

// SW128 descriptor (LBO=1, SBO=64, version=1): rows of 128B, K-major.
__device__ __forceinline__ uint64_t mk_desc(uint32_t addr) {
    constexpr uint64_t BASE = (2ull << 61) | (1ull << 46) | (64ull << 32) | (1ull << 16);
    return BASE | ((uint64_t)(addr >> 4) & 0x3FFF);
}

// cg1 kind::f16 SS MMA (bf16 in, fp32 acc)
__device__ __forceinline__ void mma_f16_ss(uint32_t d, uint64_t a, uint64_t b,
                                           uint32_t idesc, bool acc) {
    uint32_t en = acc ? 1u : 0u;
    asm volatile("{\n\t.reg .pred p;\n\tsetp.ne.u32 p, %5, 0;\n\t"
        "tcgen05.mma.cta_group::1.kind::f16 [%0], %1, %2, %3, {%4, %4, %4, %4}, p;\n\t}"
        :: "r"(d), "l"(a), "l"(b), "r"(idesc), "r"(0u), "r"(en) : "memory");
}
#endif // HAS_TCGEN05

// --------------------------- prep kernels -----------------------------------
// Weight images in k' = kr*CIN + ch order (matches node-major gather).
__global__ void prep_w_kernel(const float* __restrict__ W1,
                              const float* __restrict__ W2,
                              const float* __restrict__ W3) {
    int bid = blockIdx.x;
    const float* W; __nv_bfloat16 *gh, *gl; int COUT, CIN, chunk, HALVES;
    if (bid < 6)       { W = W1; gh = g_W1h; gl = g_W1l; COUT = 256; CIN = 128; chunk = bid;      HALVES = 2; }
    else if (bid < 18) { W = W2; gh = g_W2h; gl = g_W2l; COUT = 128; CIN = 256; chunk = bid - 6;  HALVES = 1; }
    else               { W = W3; gh = g_W3h; gl = g_W3l; COUT = 64;  CIN = 128; chunk = bid - 18; HALVES = 1; }
    const int ROWS = HALVES * 128;
    const int K = 3 * CIN;
    const int kr  = (chunk * 64) / CIN;
    const int ch0 = chunk * 64 - kr * CIN;
    char* bh = (char*)gh + (size_t)chunk * HALVES * 16384;
    char* bl = (char*)gl + (size_t)chunk * HALVES * 16384;
    for (int i = threadIdx.x; i < ROWS * 64; i += blockDim.x) {
        int o = i >> 6, k = i & 63;
        float w = (o < COUT) ? W[(size_t)o * K + (ch0 + k) * 3 + kr] : 0.f;
        __nv_bfloat16 h = __float2bfloat16(w);
        __nv_bfloat16 l = __float2bfloat16(w - __bfloat162float(h));
        uint32_t off = (uint32_t)(o >> 7) * 16384u + swz((uint32_t)((o & 127) * 128 + k * 2));
        *(__nv_bfloat16*)(bh + off) = h;
        *(__nv_bfloat16*)(bl + off) = l;
    }
}

// Transpose + pack trees: [b][c][n] -> g_X0 [b][n][c], via 32x33 smem tiles.
__global__ void prep_x_kernel(const float* __restrict__ trees) {
    __shared__ float tile[32][33];
    const int b = blockIdx.x;
    const int w = threadIdx.x >> 5, l = threadIdx.x & 31;
    const float* Tb = trees + (size_t)b * 16384;
    uint32_t* Xb = g_X0 + (size_t)b * 16384;
    for (int tc = 0; tc < 4; tc++)
        for (int tn = 0; tn < 4; tn++) {
            __syncthreads();
            #pragma unroll
            for (int rr = 0; rr < 4; rr++) {
                int r = w + rr * 8;
                tile[r][l] = Tb[(tc * 32 + r) * 128 + tn * 32 + l];
            }
            __syncthreads();
            #pragma unroll
            for (int rr = 0; rr < 4; rr++) {
                int r = w + rr * 8;
                Xb[(tn * 32 + r) * 128 + tc * 32 + l] = pack_hl(tile[l][r]);
            }
        }
}

// ------------------------------ conv layer (persistent) ---------------------
template <int CIN, int COUT, int LAYER>
__global__ __launch_bounds__(256, 1) void conv_tc(
    const int*   __restrict__ indexes,
    const float* __restrict__ Wraw,          // fallback only
    const float* __restrict__ bias,
    const float* __restrict__ W4, const float* __restrict__ b4,
    const float* __restrict__ W5, const float* __restrict__ b5,
    float* __restrict__ out)
{
    constexpr int K = 3 * CIN;
    constexpr int NCHUNK = K / 64;
    constexpr int HALVES = (COUT + 127) / 128;
    constexpr int A_BYTES = HALVES * 16384;           // one precision
    constexpr int AB_STAGE = 2 * A_BYTES + 32768;     // Ah+Al+Bh+Bl per stage
    constexpr int TBYTES = COUT * 129 * 4;
    constexpr int REGION = (2 * AB_STAGE > TBYTES) ? 2 * AB_STAGE : TBYTES;
    constexpr int OFF_IDX = REGION;
    constexpr int OFF_MBAR = OFF_IDX + 1536;
    constexpr int OFF_RED = OFF_MBAR + 48;

    extern __shared__ __align__(1024) char smem[];
    int*   sidx  = (int*)(smem + OFF_IDX);
    float* snorm = (float*)(smem + OFF_MBAR + 16);
    float* sred  = (float*)(smem + OFF_RED);

    const int tid = threadIdx.x, wid = tid >> 5, lid = tid & 31;

    const uint32_t* __restrict__ Xin =
        (LAYER == 1) ? g_X0 : (LAYER == 2) ? g_X1 : g_X2;
    uint32_t* __restrict__ Xout = (LAYER == 1) ? g_X1 : g_X2;

#if HAS_TCGEN05
    // ===================== tcgen05 tensor-core path =========================
    constexpr uint32_t IDESC = (1u << 4) | (1u << 7) | (1u << 10)
                             | (8u << 17) | (8u << 24);   // f32acc bf16 N=64 M=128
    constexpr int NCOLS = HALVES * 128;

    const uint32_t sb = smem_u32(smem);

    if (wid == 0) { TCGEN05_ALLOC(sb + OFF_MBAR + 32, NCOLS); }
    if (tid == 0) { MBARRIER_INIT(sb + OFF_MBAR, 1); MBARRIER_INIT(sb + OFF_MBAR + 8, 1); }
    __syncthreads();
    const uint32_t tmem = *(volatile uint32_t*)(smem + OFF_MBAR + 32);

    const char* gWh = (LAYER == 1) ? (const char*)g_W1h :
                      (LAYER == 2) ? (const char*)g_W2h : (const char*)g_W3h;
    const char* gWl = (LAYER == 1) ? (const char*)g_W1l :
                      (LAYER == 2) ? (const char*)g_W2l : (const char*)g_W3l;

    const int nl = lid >> 4;          // row-in-pair
    const int q  = lid & 15;          // uint4 index within a 256B row

    int use[2] = {0, 0};

    for (int b = blockIdx.x; b < B_TREES; b += GRID_P) {
        const uint32_t* __restrict__ Xb = Xin + (size_t)b * 128 * CIN;

        for (int i = tid; i < 384; i += 256)
            sidx[i] = (i < 381) ? indexes[b * 381 + i] : 0;
        __syncthreads();

        // ---- node table in registers (static-indexed; chunk loop unrolled) --
        int nd[3][8];
        #pragma unroll
        for (int it = 0; it < 8; it++) {
            int n = it * 16 + wid * 2 + nl;
            #pragma unroll
            for (int kr = 0; kr < 3; kr++) nd[kr][it] = sidx[n * 3 + kr];
        }

        // ---- prefetch B for chunk 0 ----
        uint4 v[8];
        #pragma unroll
        for (int it = 0; it < 8; it++)
            v[it] = *(const uint4*)(Xb + (size_t)nd[0][it] * CIN + q * 4);

        #pragma unroll
        for (int c0 = 0; c0 < NCHUNK; c0++) {
            const int s = c0 & 1;
            const int SA = s * AB_STAGE;
            const int OFF_AH = SA, OFF_AL = SA + A_BYTES;
            const int OFF_BH = SA + 2 * A_BYTES, OFF_BL = SA + 2 * A_BYTES + 16384;

            if (use[s] > 0)
                MBARRIER_WAIT_PARITY(sb + OFF_MBAR + s * 8, (use[s] - 1) & 1);

            // ---- A: cp.async copy of pre-swizzled W chunk (no reg round-trip)
            {
                const char* srch = gWh + (size_t)c0 * A_BYTES;
                const char* srcl = gWl + (size_t)c0 * A_BYTES;
                #pragma unroll
                for (int i = 0; i < A_BYTES / 16 / 256; i++) {
                    int idx = (tid + i * 256) * 16;
                    cp_async16(sb + OFF_AH + idx, srch + idx);
                    cp_async16(sb + OFF_AL + idx, srcl + idx);
                }
                CP_ASYNC_COMMIT();
            }

            // ---- B: split prefetched regs, swizzled STS ----
            #pragma unroll
            for (int it = 0; it < 8; it++) {
                int n = it * 16 + wid * 2 + nl;
                uint32_t h0 = __byte_perm(v[it].x, v[it].y, 0x5410);
                uint32_t h1 = __byte_perm(v[it].z, v[it].w, 0x5410);
                uint32_t l0 = __byte_perm(v[it].x, v[it].y, 0x7632);
                uint32_t l1 = __byte_perm(v[it].z, v[it].w, 0x7632);
                uint32_t off = swz((uint32_t)(n * 128 + q * 8));
                STS64(sb + OFF_BH + off, h0, h1);
                STS64(sb + OFF_BL + off, l0, l1);
            }

            // ---- prefetch B for chunk c0+1 (latency overlaps MMA/sync) ----
            if (c0 + 1 < NCHUNK) {
                const int krn  = ((c0 + 1) * 64) / CIN;
                const int chn0 = (c0 + 1) * 64 - krn * CIN;
                #pragma unroll
                for (int it = 0; it < 8; it++)
                    v[it] = *(const uint4*)(Xb + (size_t)nd[krn][it] * CIN + chn0 + q * 4);
            }

            CP_ASYNC_WAIT0();
            FENCE_ASYNC_SHARED();
            __syncthreads();

            // ---- issue MMAs for this chunk (M=128, N=64 each) ----
            if (wid == 0 && elect_one()) {
                TCGEN05_FENCE_AFTER();
                #pragma unroll
                for (int h = 0; h < HALVES; h++) {
                    uint64_t adh = mk_desc(sb + OFF_AH + h * 16384);
                    uint64_t adl = mk_desc(sb + OFF_AL + h * 16384);
                    #pragma unroll
                    for (int nh = 0; nh < 2; nh++) {
                        uint32_t d = tmem + h * 128 + nh * 64;
                        uint64_t bdh = mk_desc(sb + OFF_BH + nh * 8192);
                        uint64_t bdl = mk_desc(sb + OFF_BL + nh * 8192);
                        #pragma unroll
                        for (int p3 = 0; p3 < 3; p3++) {     // hh, lh, hl
                            uint64_t ad = (p3 == 1) ? adl : adh;
                            uint64_t bd = (p3 == 2) ? bdl : bdh;
                            #pragma unroll
                            for (int km = 0; km < 4; km++) {
                                bool acc = !(c0 == 0 && p3 == 0 && km == 0);
                                mma_f16_ss(d, ad + km * 2, bd + km * 2, IDESC, acc);
                            }
                        }
                    }
                }
                TCGEN05_COMMIT(sb + OFF_MBAR + s * 8);
            }
            use[s]++;
        }

        // ---- drain both buffers, then epilogue ----
        #pragma unroll
        for (int s = 0; s < 2; s++)
            if (use[s] > 0)
                MBARRIER_WAIT_PARITY(sb + OFF_MBAR + s * 8, (use[s] - 1) & 1);
        TCGEN05_FENCE_AFTER();

        // pass 1: LDTM once, stash raw+bias into T (col0 = 0), stats
        float* T = (float*)smem;
        float s1 = 0.f, s2 = 0.f;
        constexpr int NWARP = (LAYER == 3) ? 2 : 4;
        if (wid < NWARP) {
            #pragma unroll
            for (int h = 0; h < HALVES; h++) {
                int row = wid * 32 + lid;
                int o = h * 128 + row;
                if (o < COUT) {
                    float bv = bias[o];
                    float* Tr = T + o * 129;
                    Tr[0] = 0.f;
                    #pragma unroll
                    for (int nb = 0; nb < 4; nb++) {
                        uint32_t r[32];
                        TCGEN05_LD_X32(r, tmem + h * 128 + nb * 32);
                        TCGEN05_WAIT_LD();
                        #pragma unroll
                        for (int qq = 0; qq < 32; qq++) {
                            int n = nb * 32 + qq;
                            if (n < 127) {
                                float val = __uint_as_float(r[qq]) + bv;
                                Tr[n + 1] = val;
                                s1 += val; s2 += val * val;
                            }
                        }
                    }
                }
            }
            TCGEN05_FENCE_BEFORE();
        }
        sred[tid] = s1; sred[256 + tid] = s2;
        __syncthreads();
        #pragma unroll
        for (int st = 128; st > 0; st >>= 1) {
            if (tid < st) { sred[tid] += sred[tid + st]; sred[256 + tid] += sred[256 + tid + st]; }
            __syncthreads();
        }
        if (tid == 0) {
            constexpr float np = (float)(COUT * 128);
            float t1 = sred[0], t2 = sred[256];
            float mmu = t1 / np;
            float var = fmaxf((t2 - t1 * mmu) / (np - 1.f), 0.f);
            snorm[0] = mmu;
            snorm[1] = 1.f / (sqrtf(var) + 1e-5f);
        }
        __syncthreads();
        const float mu = snorm[0], scale = snorm[1];

        if (LAYER < 3) {
            // pass 2: normalize + leaky + pack, store NODE-MAJOR (coalesced in o)
            for (int i = tid; i < 128 * COUT; i += 256) {
                int node = i / COUT, o = i - node * COUT;
                float vv = (T + o * 129)[node];     // stride 129: conflict-free
                Xout[((size_t)b * 128 + node) * COUT + o] =
                    pack_hl(leaky((vv - mu) * scale));
            }
        } else {
            // fused maxpool + MLP  (LN3 has no leaky; scale>0 => max commutes)
            float* pooled = sred;
            float* hbuf = sred + 96;
            if (tid < 64) {
                const float* Tr = T + tid * 129;
                float mx = Tr[0];
                #pragma unroll
                for (int c = 1; c < 128; c++) mx = fmaxf(mx, Tr[c]);
                pooled[tid] = (mx - mu) * scale;
            }
            __syncthreads();
            if (tid < 32) {
                float acc = b4[tid];
                #pragma unroll
                for (int c = 0; c < 64; c++) acc += pooled[c] * W4[tid * 64 + c];
                hbuf[tid] = leaky(acc);
            }
            __syncthreads();
            if (tid < 32) {
                float p = hbuf[tid] * W5[tid];
                #pragma unroll
                for (int off = 16; off; off >>= 1) p += __shfl_down_sync(0xffffffffu, p, off);
                if (tid == 0) out[b] = p + b5[0];
            }
        }
        __syncthreads();
    }

    // ---- one-time teardown ----
    if (tid == 0) { MBARRIER_INVAL(sb + OFF_MBAR); MBARRIER_INVAL(sb + OFF_MBAR + 8); }
    __syncthreads();
    if (wid == 0) { TCGEN05_RELINQ(); TCGEN05_DEALLOC(tmem, NCOLS); }

#else
    // ===================== SIMT fp32 fallback (generic target) ==============
    float* Ws  = (float*)smem;                  // 64 x 32
    float* Bsf = (float*)(smem + 8192);         // 32 x 68 (padded)
    const int tx = tid & 15, ty = tid >> 4;

    for (int b = blockIdx.x; b < B_TREES; b += GRID_P) {
        const uint32_t* __restrict__ Xb = Xin + (size_t)b * 128 * CIN;
        __syncthreads();
        for (int i = tid; i < 384; i += 256)
            sidx[i] = (i < 381) ? indexes[b * 381 + i] : 0;
        __syncthreads();
        float s1 = 0.f, s2 = 0.f;

        for (int ot = 0; ot < COUT / 64; ot++) {
            for (int mt = 0; mt < 2; mt++) {
                float acc[4][4];
                #pragma unroll
                for (int i = 0; i < 4; i++)
                    #pragma unroll
                    for (int j = 0; j < 4; j++) acc[i][j] = 0.f;
                int o0 = ot * 64, m0 = mt * 64;
                for (int k0 = 0; k0 < K; k0 += 32) {
                    __syncthreads();
                    for (int i = tid; i < 2048; i += 256) {
                        int r = i >> 5, kk = i & 31;
                        Ws[r * 32 + kk] = Wraw[(size_t)(o0 + r) * K + k0 + kk];
                    }
                    for (int i = tid; i < 2048; i += 256) {
                        int kk = i >> 6, n = i & 63;
                        int j = k0 + kk;
                        int ch = j / 3, kr = j - 3 * ch;
                        int node = sidx[(m0 + n) * 3 + kr];
                        Bsf[kk * 68 + n] = unpack_hl(Xb[(size_t)node * CIN + ch]);
                    }
                    __syncthreads();
                    #pragma unroll
                    for (int kk = 0; kk < 32; kk++) {
                        float bvv[4];
                        #pragma unroll
                        for (int j = 0; j < 4; j++) bvv[j] = Bsf[kk * 68 + tx * 4 + j];
                        #pragma unroll
                        for (int i = 0; i < 4; i++) {
                            float av = Ws[(ty * 4 + i) * 32 + kk];
                            #pragma unroll
                            for (int j = 0; j < 4; j++) acc[i][j] += av * bvv[j];
                        }
                    }
                }
                __syncthreads();
                #pragma unroll
                for (int i = 0; i < 4; i++) {
                    int o = o0 + ty * 4 + i;
                    float bv = bias[o];
                    #pragma unroll
                    for (int j = 0; j < 4; j++) {
                        int m = m0 + tx * 4 + j;
                        if (m < 127) {
                            float val = acc[i][j] + bv;
                            g_raw[((size_t)b * COUT + o) * 128 + m] = val;
                            s1 += val; s2 += val * val;
                        }
                    }
                }
            }
        }
        sred[tid] = s1; sred[256 + tid] = s2;
        __syncthreads();
        #pragma unroll
        for (int st = 128; st > 0; st >>= 1) {
            if (tid < st) { sred[tid] += sred[tid + st]; sred[256 + tid] += sred[256 + tid + st]; }
            __syncthreads();
        }
        if (tid == 0) {
            float np = (float)(COUT * 128);
            float t1 = sred[0], t2 = sred[256];
            float mmu = t1 / np;
            float var = fmaxf((t2 - t1 * mmu) / (np - 1.f), 0.f);
            snorm[0] = mmu;
            snorm[1] = 1.f / (sqrtf(var) + 1e-5f);
        }
        __syncthreads();
        float mu = snorm[0], scale = snorm[1];

        if (LAYER < 3) {
            for (int i = tid; i < 128 * COUT; i += 256) {
                int node = i / COUT, o = i - node * COUT;
                float vv = (node == 0) ? 0.f : g_raw[((size_t)b * COUT + o) * 128 + node - 1];
                Xout[((size_t)b * 128 + node) * COUT + o] = pack_hl(leaky((vv - mu) * scale));
            }
        } else {
            float* pooled = sred;
            float* hbuf = sred + 96;
            if (tid < 64) {
                float mx = 0.f;
                for (int m = 0; m < 127; m++)
                    mx = fmaxf(mx, g_raw[((size_t)b * 64 + tid) * 128 + m]);
                pooled[tid] = (mx - mu) * scale;
            }
            __syncthreads();
            if (tid < 32) {
                float acc = b4[tid];
                #pragma unroll
                for (int c = 0; c < 64; c++) acc += pooled[c] * W4[tid * 64 + c];
                hbuf[tid] = leaky(acc);
            }
            __syncthreads();
            if (tid < 32) {
                float p = hbuf[tid] * W5[tid];
                #pragma unroll
                for (int off = 16; off; off >>= 1) p += __shfl_down_sync(0xffffffffu, p, off);
                if (tid == 0) out[b] = p + b5[0];
            }
        }
        __syncthreads();
    }
#endif
}

// ---------------------------------------------------------------------------
extern "C" void kernel_launch(void* const* d_in, const int* in_sizes, int n_in,
                              void* d_out, int out_size)
{
    const float *trees, *W1, *b1, *W2, *b2, *W3, *b3, *W4, *b4, *W5, *b5;
    const int* indexes;

    if (in_sizes[1] == 3 * 127 * B_TREES) {
        trees   = (const float*)d_in[0];
        indexes = (const int*)  d_in[1];
        W1 = (const float*)d_in[2];  b1 = (const float*)d_in[3];
        W2 = (const float*)d_in[4];  b2 = (const float*)d_in[5];
        W3 = (const float*)d_in[6];  b3 = (const float*)d_in[7];
        W4 = (const float*)d_in[8];  b4 = (const float*)d_in[9];
        W5 = (const float*)d_in[10]; b5 = (const float*)d_in[11];
    } else {
        trees = (const float*)d_in[0];
        W1 = (const float*)d_in[1];  b1 = (const float*)d_in[2];
        W2 = (const float*)d_in[3];  b2 = (const float*)d_in[4];
        W3 = (const float*)d_in[5];  b3 = (const float*)d_in[6];
        W4 = (const float*)d_in[7];  b4 = (const float*)d_in[8];
        W5 = (const float*)d_in[9];  b5 = (const float*)d_in[10];
        indexes = (const int*)d_in[11];
    }
    float* out = (float*)d_out;

    const int SMEM1 = 196608 + 1536 + 48 + 2048;   // 200240
    const int SMEM2 = 131072 + 1536 + 48 + 2048;   // 134704
    cudaFuncSetAttribute(conv_tc<128, 256, 1>, cudaFuncAttributeMaxDynamicSharedMemorySize, SMEM1);
    cudaFuncSetAttribute(conv_tc<256, 128, 2>, cudaFuncAttributeMaxDynamicSharedMemorySize, SMEM2);
    cudaFuncSetAttribute(conv_tc<128, 64, 3>,  cudaFuncAttributeMaxDynamicSharedMemorySize, SMEM2);

    prep_w_kernel<<<24, 256>>>(W1, W2, W3);
    prep_x_kernel<<<B_TREES, 256>>>(trees);
    conv_tc<128, 256, 1><<<GRID_P, 256, SMEM1>>>(indexes, W1, b1, nullptr, nullptr, nullptr, nullptr, nullptr);
    conv_tc<256, 128, 2><<<GRID_P, 256, SMEM2>>>(indexes, W2, b2, nullptr, nullptr, nullptr, nullptr, nullptr);
    conv_tc<128, 64, 3><<<GRID_P, 256, SMEM2>>>(indexes, W3, b3, W4, b4, W5, b5, out);
}